// round 1
// baseline (speedup 1.0000x reference)
#include <cuda_runtime.h>
#include <math.h>

#define BB 2
#define SS 2048
#define DD 1024
#define HH 16
#define HD 64
#define MTOK (BB*SS)   // 4096

// Scratch (allocation-free rule: __device__ globals)
__device__ float g_qkv[BB*SS*3*DD];   // [B*S, 3D]
__device__ float g_attn[BB*SS*DD];    // [B*S, D]

// ---------------------------------------------------------------------------
// C[M,N] = A[M,K] @ W[N,K]^T + bias[N]   (torch Linear: y = x W^T + b)
// 64x64 block tile, 256 threads, 4x4 register tile per thread, BK=16.
// ---------------------------------------------------------------------------
__global__ void gemm_nt_kernel(const float* __restrict__ A,
                               const float* __restrict__ W,
                               const float* __restrict__ bias,
                               float* __restrict__ C,
                               int M, int N, int K) {
    __shared__ float As[64][17];
    __shared__ float Ws[64][17];
    const int tid = threadIdx.x;
    const int tx = tid & 15;
    const int ty = tid >> 4;
    const int row0 = blockIdx.y * 64;
    const int col0 = blockIdx.x * 64;

    float acc[4][4] = {};

    for (int k0 = 0; k0 < K; k0 += 16) {
        // 64x16 tiles, 1024 elems, 256 threads -> 4 each
        #pragma unroll
        for (int t = tid; t < 64*16; t += 256) {
            int r = t >> 4, c = t & 15;
            As[r][c] = A[(size_t)(row0 + r) * K + k0 + c];
            Ws[r][c] = W[(size_t)(col0 + r) * K + k0 + c];
        }
        __syncthreads();
        #pragma unroll
        for (int kk = 0; kk < 16; kk++) {
            float a[4], w[4];
            #pragma unroll
            for (int i = 0; i < 4; i++) a[i] = As[ty*4 + i][kk];
            #pragma unroll
            for (int j = 0; j < 4; j++) w[j] = Ws[tx*4 + j][kk];
            #pragma unroll
            for (int i = 0; i < 4; i++)
                #pragma unroll
                for (int j = 0; j < 4; j++)
                    acc[i][j] += a[i] * w[j];
        }
        __syncthreads();
    }

    #pragma unroll
    for (int i = 0; i < 4; i++) {
        int r = row0 + ty*4 + i;
        #pragma unroll
        for (int j = 0; j < 4; j++) {
            int c = col0 + tx*4 + j;
            C[(size_t)r * N + c] = acc[i][j] + bias[c];
        }
    }
}

// ---------------------------------------------------------------------------
// Flash-attention style causal MHA, fp32.
// One CTA = (batch b, head h, 64-row q tile). 256 threads (16x16), each owns
// a 4x4 fragment of the 64x64 S tile and of the 64x64 O accumulator.
// ---------------------------------------------------------------------------
struct AttnSmem {
    float Qs[64][65];
    float Ks[64][65];
    float Vs[64][65];
    float Ps[64][65];
    float m_s[64];
    float l_s[64];
    float redm[64][16];
    float reds[64][16];
};

__global__ void attn_kernel(const float* __restrict__ qkv,
                            float* __restrict__ outp) {
    extern __shared__ char smem_raw[];
    AttnSmem& sm = *reinterpret_cast<AttnSmem*>(smem_raw);

    const int qt = blockIdx.x;   // 0..31
    const int h  = blockIdx.y;   // 0..15
    const int b  = blockIdx.z;   // 0..1
    const int tid = threadIdx.x;
    const int tx = tid & 15;
    const int ty = tid >> 4;
    const int q0 = qt * 64;

    // Load Q tile [64 x 64]
    for (int t = tid; t < 64*64; t += 256) {
        int r = t >> 6, d = t & 63;
        sm.Qs[r][d] = qkv[(size_t)(b*SS + q0 + r) * (3*DD) + h*HD + d];
    }
    if (tid < 64) { sm.m_s[tid] = -1e30f; sm.l_s[tid] = 0.0f; }

    float acc[4][4] = {};

    for (int kt = 0; kt <= qt; kt++) {
        const int k0 = kt * 64;
        __syncthreads();   // prev-iter Ks/Vs/Ps reads done; Q load done (iter 0)

        // Load K and V tiles
        for (int t = tid; t < 64*64; t += 256) {
            int r = t >> 6, d = t & 63;
            size_t base = (size_t)(b*SS + k0 + r) * (3*DD) + h*HD + d;
            sm.Ks[r][d] = qkv[base + DD];
            sm.Vs[r][d] = qkv[base + 2*DD];
        }
        __syncthreads();

        // S = Q K^T (4x4 fragment per thread)
        float s[4][4] = {};
        #pragma unroll 8
        for (int d = 0; d < 64; d++) {
            float a[4], kf[4];
            #pragma unroll
            for (int i = 0; i < 4; i++) a[i] = sm.Qs[ty*4 + i][d];
            #pragma unroll
            for (int j = 0; j < 4; j++) kf[j] = sm.Ks[tx*4 + j][d];
            #pragma unroll
            for (int i = 0; i < 4; i++)
                #pragma unroll
                for (int j = 0; j < 4; j++)
                    s[i][j] += a[i] * kf[j];
        }

        // scale + causal mask + local row max
        #pragma unroll
        for (int i = 0; i < 4; i++) {
            int qg = q0 + ty*4 + i;
            float lm = -1e30f;
            #pragma unroll
            for (int j = 0; j < 4; j++) {
                int kg = k0 + tx*4 + j;
                float v = (kg <= qg) ? s[i][j] * 0.125f : -1e30f;
                s[i][j] = v;
                lm = fmaxf(lm, v);
            }
            sm.redm[ty*4 + i][tx] = lm;
        }
        __syncthreads();

        // online softmax update
        float scale_i[4], newm[4];
        #pragma unroll
        for (int i = 0; i < 4; i++) {
            int row = ty*4 + i;
            float tm = -1e30f;
            #pragma unroll
            for (int t2 = 0; t2 < 16; t2++) tm = fmaxf(tm, sm.redm[row][t2]);
            float om = sm.m_s[row];
            float nm = fmaxf(om, tm);
            newm[i] = nm;
            scale_i[i] = __expf(om - nm);
            float ls = 0.0f;
            #pragma unroll
            for (int j = 0; j < 4; j++) {
                float p = __expf(s[i][j] - nm);
                sm.Ps[row][tx*4 + j] = p;
                ls += p;
            }
            sm.reds[row][tx] = ls;
            #pragma unroll
            for (int j = 0; j < 4; j++) acc[i][j] *= scale_i[i];
        }
        __syncthreads();

        if (tx == 0) {
            #pragma unroll
            for (int i = 0; i < 4; i++) {
                int row = ty*4 + i;
                float tot = 0.0f;
                #pragma unroll
                for (int t2 = 0; t2 < 16; t2++) tot += sm.reds[row][t2];
                sm.l_s[row] = sm.l_s[row] * scale_i[i] + tot;
                sm.m_s[row] = newm[i];
            }
        }

        // O += P @ V
        #pragma unroll 8
        for (int c = 0; c < 64; c++) {
            float p[4], v[4];
            #pragma unroll
            for (int i = 0; i < 4; i++) p[i] = sm.Ps[ty*4 + i][c];
            #pragma unroll
            for (int j = 0; j < 4; j++) v[j] = sm.Vs[c][tx*4 + j];
            #pragma unroll
            for (int i = 0; i < 4; i++)
                #pragma unroll
                for (int j = 0; j < 4; j++)
                    acc[i][j] += p[i] * v[j];
        }
    }
    __syncthreads();   // final l_s writes visible

    // normalize and store to [B, S, H*Hd] layout
    #pragma unroll
    for (int i = 0; i < 4; i++) {
        int row = ty*4 + i;
        float inv = 1.0f / sm.l_s[row];
        #pragma unroll
        for (int j = 0; j < 4; j++) {
            outp[(size_t)(b*SS + q0 + row) * DD + h*HD + tx*4 + j] = acc[i][j] * inv;
        }
    }
}

// ---------------------------------------------------------------------------
extern "C" void kernel_launch(void* const* d_in, const int* in_sizes, int n_in,
                              void* d_out, int out_size) {
    const float* x     = (const float*)d_in[0];
    const float* W_qkv = (const float*)d_in[1];
    const float* b_qkv = (const float*)d_in[2];
    const float* W_out = (const float*)d_in[3];
    const float* b_out = (const float*)d_in[4];
    float* out = (float*)d_out;

    float *qkv_ptr = nullptr, *attn_ptr = nullptr;
    cudaGetSymbolAddress((void**)&qkv_ptr, g_qkv);
    cudaGetSymbolAddress((void**)&attn_ptr, g_attn);

    cudaFuncSetAttribute(attn_kernel,
                         cudaFuncAttributeMaxDynamicSharedMemorySize,
                         (int)sizeof(AttnSmem));

    // 1) QKV projection: [4096,1024] @ [3072,1024]^T -> [4096,3072]
    gemm_nt_kernel<<<dim3(3*DD/64, MTOK/64), 256>>>(x, W_qkv, b_qkv, qkv_ptr,
                                                    MTOK, 3*DD, DD);

    // 2) causal attention -> [B*S, D]
    attn_kernel<<<dim3(SS/64, HH, BB), 256, sizeof(AttnSmem)>>>(qkv_ptr, attn_ptr);

    // 3) output projection: [4096,1024] @ [1024,1024]^T -> [4096,1024]
    gemm_nt_kernel<<<dim3(DD/64, MTOK/64), 256>>>(attn_ptr, W_out, b_out, out,
                                                  MTOK, DD, DD);
}